// round 15
// baseline (speedup 1.0000x reference)
#include <cuda_runtime.h>
#include <cuda_bf16.h>
#include <math.h>
#include <stdint.h>

#define Bsz 8
#define Sq  512
#define Dm  512
#define Hh  8
#define DK  64
#define FF  2048
#define MTOK (Bsz*Sq)   // 4096
#define NCPT 1000
#define NBH (Bsz*Hh)    // 64

// ---------------- scratch (device globals; no allocation) ----------------
__device__ float g_y [MTOK*Dm];
__device__ float g_x [MTOK*Dm];
__device__ float g_QV[MTOK*1024];
__device__ float g_Ob[MTOK*Dm];
__device__ float g_T1[MTOK*Dm];
__device__ float g_S [NBH*Sq*Sq];          // 64 MB scores
__device__ float g_bqv[6*1024];
// split (hi/lo bf16 pair-packed) activations: uint2 per k-pair
__device__ uint2 g_x0s[MTOK*256];
__device__ uint2 g_ys [MTOK*256];
__device__ uint2 g_xs [MTOK*256];
__device__ uint2 g_T1s[MTOK*256];
__device__ uint2 g_Abs[MTOK*256];
__device__ uint2 g_Hfs[MTOK*1024];
__device__ uint2 g_Ccs[MTOK*512];
__device__ uint2 g_M1s[MTOK*256];
__device__ uint2 g_M2s[MTOK*512];
__device__ uint2 g_QVs[MTOK*512];          // split Q|V (Q part used)
__device__ uint2 g_Ks [MTOK*256];          // split K (layers 0-1)
__device__ uint2 g_Vts[NBH*64*256];        // split V^T per (b,h): [d][seq-pair]
// split weights (k-pair packed [K/2][N])
__device__ uint2 g_Wqvs[6*256*1024];
__device__ uint2 g_Wos [6*256*512];
__device__ uint2 g_W1s [6*256*2048];
__device__ uint2 g_W2s [6*1024*512];
__device__ uint2 g_oW0s[512*512];
__device__ uint2 g_oW1s[256*1024];
__device__ uint2 g_oW2s[512*1000];

// ---------------- split helper ----------------
__device__ __forceinline__ uint2 split2(float v0, float v1) {
    __nv_bfloat16 h0 = __float2bfloat16(v0);
    __nv_bfloat16 h1 = __float2bfloat16(v1);
    float r0 = v0 - __bfloat162float(h0);
    float r1 = v1 - __bfloat162float(h1);
    __nv_bfloat162 hh; hh.x = h0; hh.y = h1;
    __nv_bfloat162 ll = __floats2bfloat162_rn(r0, r1);
    return make_uint2(*(uint32_t*)&hh, *(uint32_t*)&ll);
}
__device__ __forceinline__ void mma_bf16(float* c, const uint32_t* a, const uint32_t* b) {
    asm volatile(
        "mma.sync.aligned.m16n8k16.row.col.f32.bf16.bf16.f32 "
        "{%0,%1,%2,%3}, {%4,%5,%6,%7}, {%8,%9}, {%0,%1,%2,%3};"
        : "+f"(c[0]), "+f"(c[1]), "+f"(c[2]), "+f"(c[3])
        : "r"(a[0]), "r"(a[1]), "r"(a[2]), "r"(a[3]), "r"(b[0]), "r"(b[1]));
}

// ---------------- weight split: W[K][N] fp32 -> out[K/2][ldo] uint2 ----------
__global__ void split_w(const float* __restrict__ W, uint2* __restrict__ out,
                        int K, int N, int ldo, int colOff,
                        size_t inStride, size_t outStride)
{
    int z = blockIdx.z;
    const float* Wz = W + (size_t)z * inStride;
    uint2* oz = out + (size_t)z * outStride + colOff;
    int KP = K >> 1;
    int total = KP * N;
    for (int idx = blockIdx.x * blockDim.x + threadIdx.x; idx < total;
         idx += gridDim.x * blockDim.x) {
        int kp = idx / N, n = idx - kp * N;
        float v0 = Wz[(size_t)(2 * kp) * N + n];
        float v1 = Wz[(size_t)(2 * kp + 1) * N + n];
        oz[(size_t)kp * ldo + n] = split2(v0, v1);
    }
}

__global__ void pack_bqv(const float* __restrict__ bk, const float* __restrict__ bv,
                         float* __restrict__ bqv)
{
    int i = blockIdx.x * blockDim.x + threadIdx.x;
    if (i >= 6 * 1024) return;
    int li = i >> 10, j = i & 1023;
    bqv[i] = (j < 512) ? bk[li * 512 + j] : bv[li * 512 + j - 512];
}

// ---------------- embed ----------------
__global__ void embed_kernel(const int* __restrict__ c_data, const int* __restrict__ ca_data,
                             const float* __restrict__ c_emb, const float* __restrict__ ca_emb,
                             float* __restrict__ y, float* __restrict__ x,
                             uint2* __restrict__ x0s, uint2* __restrict__ ys, uint2* __restrict__ xs)
{
    int r = blockIdx.x;
    int c = c_data[r];
    int resp = (ca_data[r] - c) / NCPT;
    const float* er = c_emb + (size_t)c * Dm;
    const float* ar = ca_emb + (size_t)resp * Dm;
    int j = threadIdx.x * 4;
    float4 e4 = *(const float4*)(er + j);
    float4 a4 = *(const float4*)(ar + j);
    float y0 = e4.x + a4.x, y1 = e4.y + a4.y, y2 = e4.z + a4.z, y3 = e4.w + a4.w;
    *(float4*)&x[(size_t)r*Dm + j] = e4;
    *(float4*)&y[(size_t)r*Dm + j] = make_float4(y0, y1, y2, y3);
    size_t sb = (size_t)r * 256 + (j >> 1);
    uint2 s0 = split2(e4.x, e4.y), s1 = split2(e4.z, e4.w);
    x0s[sb] = s0; x0s[sb + 1] = s1;
    xs [sb] = s0; xs [sb + 1] = s1;
    ys [sb] = split2(y0, y1); ys[sb + 1] = split2(y2, y3);
}

// ---------------- bf16x3 tensor-core GEMM, 128x64 tile, K32 chunks ----------
#define GP 138

__global__ __launch_bounds__(256, 2)
void gemm_hl64(const uint2* __restrict__ Ahl, const uint2* __restrict__ Whl, int ldw,
               const float* __restrict__ bias, float* __restrict__ C, int ldc,
               uint2* __restrict__ Chl, int ldch,
               int M, int N, int K, int relu)
{
    __shared__ uint2 As[2][16][GP];
    __shared__ uint2 Bs[2][16][66];

    int tid = threadIdx.x;
    int row0 = blockIdx.y * 128, col0 = blockIdx.x * 64;
    int warp = tid >> 5, lane = tid & 31;
    int wm = warp & 3, wn = warp >> 2;      // 4x2 warps, 32x32 tiles
    int g = lane >> 2, tig = lane & 3;

    int arow = tid >> 1, aks = tid & 1;     // aks: which 8-kp half of the chunk
    int bn = tid & 63, bg = tid >> 6;       // bg: 0..3
    int KP = K >> 1;
    const uint2* Ap = Ahl + (size_t)(row0 + arow) * KP + aks * 8;
    int bcg = col0 + bn;
    bool bok = bcg < N;

    float acc[2][4][4];
#pragma unroll
    for (int i = 0; i < 2; i++)
#pragma unroll
        for (int j = 0; j < 4; j++)
#pragma unroll
            for (int q = 0; q < 4; q++) acc[i][j][q] = 0.f;

    uint2 arv[8], brv[4];
    int T = K >> 5;                          // K32 chunks

    auto ldg = [&](int t) {
        const uint2* p = Ap + t * 16;
#pragma unroll
        for (int q = 0; q < 4; q++) {
            uint4 u = *(const uint4*)(p + 2 * q);
            arv[2*q]   = make_uint2(u.x, u.y);
            arv[2*q+1] = make_uint2(u.z, u.w);
        }
        if (bok) {
#pragma unroll
            for (int j = 0; j < 4; j++)
                brv[j] = Whl[(size_t)(t * 16 + bg + 4 * j) * ldw + bcg];
        } else {
#pragma unroll
            for (int j = 0; j < 4; j++) brv[j] = make_uint2(0, 0);
        }
    };
    auto sts = [&](int bf) {
        // A: kp' = jj (0..7) within half aks -> slot = aks*8? NO:
        // chunk kp l = aks*8 + jj; step s = l>>3 = aks; l' = jj
        // slot = 8*aks + (jj&3)*2 + (jj>>2)
#pragma unroll
        for (int jj = 0; jj < 8; jj++)
            As[bf][aks * 8 + (jj & 3) * 2 + (jj >> 2)][arow] = arv[jj];
        // B: l = bg + 4j -> s = j>>1; slot = 8*(j>>1) + 2*bg + (j&1)
#pragma unroll
        for (int j = 0; j < 4; j++)
            Bs[bf][8 * (j >> 1) + 2 * bg + (j & 1)][bn] = brv[j];
    };

    ldg(0); sts(0);
    __syncthreads();

    int buf = 0;
    for (int t = 0; t < T; t++) {
        if (t + 1 < T) ldg(t + 1);
#pragma unroll
        for (int s = 0; s < 2; s++) {
            int so = s * 8;
            uint32_t ah[2][4], al[2][4];
#pragma unroll
            for (int mt = 0; mt < 2; mt++) {
                int r = wm * 32 + mt * 16 + g;
                uint2 ua = As[buf][so + 2*tig    ][r];
                uint2 ub = As[buf][so + 2*tig    ][r + 8];
                uint2 uc = As[buf][so + 2*tig + 1][r];
                uint2 ud = As[buf][so + 2*tig + 1][r + 8];
                ah[mt][0]=ua.x; ah[mt][1]=ub.x; ah[mt][2]=uc.x; ah[mt][3]=ud.x;
                al[mt][0]=ua.y; al[mt][1]=ub.y; al[mt][2]=uc.y; al[mt][3]=ud.y;
            }
#pragma unroll
            for (int nt = 0; nt < 4; nt++) {
                int n0 = wn * 32 + nt * 8 + g;
                uint2 u0 = Bs[buf][so + 2*tig    ][n0];
                uint2 u1 = Bs[buf][so + 2*tig + 1][n0];
                uint32_t bh[2] = {u0.x, u1.x};
                uint32_t bl[2] = {u0.y, u1.y};
#pragma unroll
                for (int mt = 0; mt < 2; mt++) {
                    mma_bf16(acc[mt][nt], ah[mt], bh);
                    mma_bf16(acc[mt][nt], al[mt], bh);
                    mma_bf16(acc[mt][nt], ah[mt], bl);
                }
            }
        }
        if (t + 1 < T) {
            sts(buf ^ 1);
            __syncthreads();
            buf ^= 1;
        }
    }

#pragma unroll
    for (int mt = 0; mt < 2; mt++) {
        int rbase = row0 + wm * 32 + mt * 16;
#pragma unroll
        for (int nt = 0; nt < 4; nt++) {
            int cb = col0 + wn * 32 + nt * 8 + 2 * tig;
            float b0 = (cb < N) ? bias[cb] : 0.f;
            float b1 = (cb + 1 < N) ? bias[cb + 1] : 0.f;
#pragma unroll
            for (int half = 0; half < 2; half++) {
                int r = rbase + g + half * 8;
                float v0 = acc[mt][nt][half * 2 + 0] + b0;
                float v1 = acc[mt][nt][half * 2 + 1] + b1;
                if (relu) { v0 = fmaxf(v0, 0.f); v1 = fmaxf(v1, 0.f); }
                if (C) {
                    if (cb < N)     C[(size_t)r * ldc + cb]     = v0;
                    if (cb + 1 < N) C[(size_t)r * ldc + cb + 1] = v1;
                }
                if (Chl && cb + 1 < N)
                    Chl[(size_t)r * ldch + (cb >> 1)] = split2(v0, v1);
            }
        }
    }
}

// ---------------- V transpose + split: Vt[z][d][seq-pair] -------------------
__global__ void vtsplit(const float* __restrict__ V, uint2* __restrict__ Vts)
{
    __shared__ float t[32][65];
    int z = blockIdx.y, b = z >> 3, h = z & 7;
    int s0 = blockIdx.x * 32;
    int tid = threadIdx.x;
    {
        int i = tid >> 3, fj = tid & 7;
        const float* src = V + (size_t)(b * Sq + s0 + i) * 1024 + h * 64 + fj * 8;
        float4 v0 = *(const float4*)src;
        float4 v1 = *(const float4*)(src + 4);
        t[i][fj*8+0] = v0.x; t[i][fj*8+1] = v0.y; t[i][fj*8+2] = v0.z; t[i][fj*8+3] = v0.w;
        t[i][fj*8+4] = v1.x; t[i][fj*8+5] = v1.y; t[i][fj*8+6] = v1.z; t[i][fj*8+7] = v1.w;
    }
    __syncthreads();
    int d = tid >> 2, q = tid & 3;
    uint2* dst = Vts + ((size_t)z * 64 + d) * 256 + (s0 >> 1);
#pragma unroll
    for (int j = 0; j < 4; j++) {
        int kp = q * 4 + j;
        dst[kp] = split2(t[2*kp][d], t[2*kp+1][d]);
    }
}

// ---------------- attention part 1: scores via tensor cores -----------------
#define SGP 130
#define SCORE_SMEM (2*4*8*SGP*(int)sizeof(uint2))
__global__ __launch_bounds__(512, 2)
void score_tc(const uint2* __restrict__ Qs, int ldq,
              const uint2* __restrict__ Ks, int ldk,
              float* __restrict__ S)
{
    int kt = blockIdx.x, qt = blockIdx.y;
    if (kt > qt) return;
    int z = blockIdx.z, b = z >> 3, h = z & 7;
    extern __shared__ uint2 sm[];
    uint2 (*As)[8][SGP] = (uint2(*)[8][SGP])sm;
    uint2 (*Bs)[8][SGP] = (uint2(*)[8][SGP])(sm + 4*8*SGP);

    int tid = threadIdx.x;
    {
        int r = tid >> 2, quarter = tid & 3;
        const uint2* qa = Qs + (size_t)(b*Sq + qt*128 + r) * ldq + h*32 + quarter*8;
        const uint2* ka = Ks + (size_t)(b*Sq + kt*128 + r) * ldk + h*32 + quarter*8;
#pragma unroll
        for (int j = 0; j < 4; j++) {
            uint4 uq = *(const uint4*)(qa + 2*j);
            uint4 uk = *(const uint4*)(ka + 2*j);
            int m0 = 2*j, m1 = 2*j + 1;
            int sl0 = (m0 & 3)*2 + (m0 >> 2);
            int sl1 = (m1 & 3)*2 + (m1 >> 2);
            As[quarter][sl0][r] = make_uint2(uq.x, uq.y);
            As[quarter][sl1][r] = make_uint2(uq.z, uq.w);
            Bs[quarter][sl0][r] = make_uint2(uk.x, uk.y);
            Bs[quarter][sl1][r] = make_uint2(uk.z, uk.w);
        }
    }
    __syncthreads();

    int warp = tid >> 5, lane = tid & 31;
    int wm = warp & 3, wn = warp >> 2;
    int g = lane >> 2, tig = lane & 3;
    float acc[2][4][4];
#pragma unroll
    for (int i = 0; i < 2; i++)
#pragma unroll
        for (int j = 0; j < 4; j++)
#pragma unroll
            for (int q = 0; q < 4; q++) acc[i][j][q] = 0.f;

#pragma unroll
    for (int c = 0; c < 4; c++) {
        uint32_t ah[2][4], al[2][4];
#pragma unroll
        for (int mt = 0; mt < 2; mt++) {
            int r = wm * 32 + mt * 16 + g;
            uint2 ua = As[c][2*tig    ][r];
            uint2 ub = As[c][2*tig    ][r + 8];
            uint2 uc = As[c][2*tig + 1][r];
            uint2 ud = As[c][2*tig + 1][r + 8];
            ah[mt][0]=ua.x; ah[mt][1]=ub.x; ah[mt][2]=uc.x; ah[mt][3]=ud.x;
            al[mt][0]=ua.y; al[mt][1]=ub.y; al[mt][2]=uc.y; al[mt][3]=ud.y;
        }
#pragma unroll
        for (int nt = 0; nt < 4; nt++) {
            int n0 = wn * 32 + nt * 8 + g;
            uint2 u0 = Bs[c][2*tig    ][n0];
            uint2 u1 = Bs[c][2*tig + 1][n0];
            uint32_t bh[2] = {u0.x, u1.x};
            uint32_t bl[2] = {u0.y, u1.y};
#pragma unroll
            for (int mt = 0; mt < 2; mt++) {
                mma_bf16(acc[mt][nt], ah[mt], bh);
                mma_bf16(acc[mt][nt], al[mt], bh);
                mma_bf16(acc[mt][nt], ah[mt], bl);
            }
        }
    }

    float* Sbase = S + ((size_t)z * Sq + qt * 128) * Sq + kt * 128;
#pragma unroll
    for (int mt = 0; mt < 2; mt++)
#pragma unroll
        for (int nt = 0; nt < 4; nt++)
#pragma unroll
            for (int half = 0; half < 2; half++) {
                int row = wm * 32 + mt * 16 + g + half * 8;
                int col = wn * 32 + nt * 8 + 2 * tig;
                float2 v = make_float2(acc[mt][nt][half*2] * 0.125f,
                                       acc[mt][nt][half*2+1] * 0.125f);
                *(float2*)&Sbase[(size_t)row * Sq + col] = v;
            }
}

// ---------------- attention part 2: warp-per-row softmax/decay (no barriers) -
__global__ __launch_bounds__(256)
void decay_softmax_warp(float* __restrict__ S, const float* __restrict__ gammas,
                        int layer, int strict)
{
    int lane = threadIdx.x & 31;
    int gw = blockIdx.x * 8 + (threadIdx.x >> 5);   // global warp id, 32768 total
    int z = gw >> 9, i = gw & 511;
    int h = z & 7;
    float* row = S + ((size_t)z * Sq + i) * Sq;
    int kmax = i - strict;
    int kend = ((i >> 7) + 1) * 128;     // av_tc reads only tiles kt <= qt
    int base = lane * 16;
    if (kmax < 0) {
        if (base < kend) {
#pragma unroll
            for (int j = 0; j < 4; j++)
                *(float4*)&row[base + 4 * j] = make_float4(0.f, 0.f, 0.f, 0.f);
        }
        return;
    }

    float v[16];
#pragma unroll
    for (int j = 0; j < 4; j++) {
        int k = base + 4 * j;
        if (k + 3 <= kmax) {
            float4 f = *(const float4*)&row[k];
            v[4*j] = f.x; v[4*j+1] = f.y; v[4*j+2] = f.z; v[4*j+3] = f.w;
        } else {
#pragma unroll
            for (int e = 0; e < 4; e++)
                v[4*j+e] = (k + e <= kmax) ? row[k + e] : 0.f;
        }
    }

    float lm = -3e38f;
#pragma unroll
    for (int j = 0; j < 16; j++) if (base + j <= kmax) lm = fmaxf(lm, v[j]);
#pragma unroll
    for (int o = 16; o; o >>= 1) lm = fmaxf(lm, __shfl_xor_sync(~0u, lm, o));
    float m1 = lm;

    float p[16];
    float ls = 0.f;
#pragma unroll
    for (int j = 0; j < 16; j++) {
        p[j] = (base + j <= kmax) ? expf(v[j] - m1) : 0.f;
        ls += p[j];
    }
    float ws = ls;
#pragma unroll
    for (int o = 16; o; o >>= 1) ws += __shfl_xor_sync(~0u, ws, o);
    float inv1 = 1.f / ws;
#pragma unroll
    for (int j = 0; j < 16; j++) p[j] *= inv1;

    float cum[16];
    float run = 0.f;
#pragma unroll
    for (int j = 0; j < 16; j++) { run += p[j]; cum[j] = run; }
    float t = run;
#pragma unroll
    for (int o = 1; o < 32; o <<= 1) {
        float tt = __shfl_up_sync(~0u, t, o);
        if (lane >= o) t += tt;
    }
    float excl  = t - run;
    float total = __shfl_sync(~0u, t, 31);

    float gm = gammas[layer * Hh + h];
    float sp = (gm > 20.f) ? gm : log1pf(expf(gm));
    float gamma = -sp;

#pragma unroll
    for (int j = 0; j < 16; j++) {
        float suf  = total - (excl + cum[j]);
        float pos  = (float)(i - (base + j));
        float dist = sqrtf(fmaxf(suf * pos, 0.f));
        float te   = fminf(fmaxf(expf(dist * gamma), 1e-5f), 1e5f);
        v[j] = v[j] * te;
    }

    lm = -3e38f;
#pragma unroll
    for (int j = 0; j < 16; j++) if (base + j <= kmax) lm = fmaxf(lm, v[j]);
#pragma unroll
    for (int o = 16; o; o >>= 1) lm = fmaxf(lm, __shfl_xor_sync(~0u, lm, o));
    float m2 = lm;

    ls = 0.f;
#pragma unroll
    for (int j = 0; j < 16; j++) {
        p[j] = (base + j <= kmax) ? expf(v[j] - m2) : 0.f;
        ls += p[j];
    }
    ws = ls;
#pragma unroll
    for (int o = 16; o; o >>= 1) ws += __shfl_xor_sync(~0u, ws, o);
    float inv2 = 1.f / ws;

    if (base < kend) {
#pragma unroll
        for (int j = 0; j < 4; j++) {
            float4 f = make_float4(p[4*j] * inv2, p[4*j+1] * inv2,
                                   p[4*j+2] * inv2, p[4*j+3] * inv2);
            *(float4*)&row[base + 4 * j] = f;
        }
    }
}

// ---------------- attention part 3: O = P @ V via tensor cores --------------
__global__ __launch_bounds__(256, 2)
void av_tc(const float* __restrict__ S, const uint2* __restrict__ Vts,
           uint2* __restrict__ Abs)
{
    __shared__ uint2 As[2][8][130];
    __shared__ uint2 Bs[2][8][66];
    int qt = blockIdx.x, z = blockIdx.y, b = z >> 3, h = z & 7;
    int tid = threadIdx.x;
    int warp = tid >> 5, lane = tid & 31;
    int wm = warp & 3, wn = warp >> 2;     // 4x2, 32q x 32d
    int g = lane >> 2, tig = lane & 3;

    int ar = tid >> 1, ahalf = tid & 1;
    const float* Sbase = S + ((size_t)z * Sq + qt * 128 + ar) * Sq + ahalf * 8;
    int bd = tid & 63, bpr = tid >> 6;
    const uint2* Vbase = Vts + ((size_t)z * 64 + bd) * 256 + bpr * 2;

    int nT = (qt + 1) * 8;
    float2 fa[4]; uint4 bu;
    auto ldg = [&](int t) {
#pragma unroll
        for (int j = 0; j < 4; j++) fa[j] = *(const float2*)(Sbase + t * 16 + 2 * j);
        bu = *(const uint4*)(Vbase + (size_t)t * 8);
    };
    auto sts = [&](int bf) {
#pragma unroll
        for (int j = 0; j < 4; j++)
            As[bf][j * 2 + ahalf][ar] = split2(fa[j].x, fa[j].y);
        int m0 = bpr * 2, m1 = bpr * 2 + 1;
        Bs[bf][(m0 & 3)*2 + (m0 >> 2)][bd] = make_uint2(bu.x, bu.y);
        Bs[bf][(m1 & 3)*2 + (m1 >> 2)][bd] = make_uint2(bu.z, bu.w);
    };

    float acc[2][4][4];
#pragma unroll
    for (int i = 0; i < 2; i++)
#pragma unroll
        for (int j = 0; j < 4; j++)
#pragma unroll
            for (int q = 0; q < 4; q++) acc[i][j][q] = 0.f;

    ldg(0); sts(0);
    __syncthreads();
    int buf = 0;
    for (int t = 0; t < nT; t++) {
        if (t + 1 < nT) ldg(t + 1);
        uint32_t ah[2][4], al[2][4];
#pragma unroll
        for (int mt = 0; mt < 2; mt++) {
            int r = wm * 32 + mt * 16 + g;
            uint2 ua = As[buf][2*tig    ][r];
            uint2 ub = As[buf][2*tig    ][r + 8];
            uint2 uc = As[buf][2*tig + 1][r];
            uint2 ud = As[buf][2*tig + 1][r + 8];
            ah[mt][0]=ua.x; ah[mt][1]=ub.x; ah[mt][2]=uc.x; ah[mt][3]=ud.x;
            al[mt][0]=ua.y; al[mt][1]=ub.y; al[mt][2]=uc.y; al[mt][3]=ud.y;
        }
#pragma unroll
        for (int nt = 0; nt < 4; nt++) {
            int n0 = wn * 32 + nt * 8 + g;
            uint2 u0 = Bs[buf][2*tig    ][n0];
            uint2 u1 = Bs[buf][2*tig + 1][n0];
            uint32_t bh[2] = {u0.x, u1.x};
            uint32_t bl[2] = {u0.y, u1.y};
#pragma unroll
            for (int mt = 0; mt < 2; mt++) {
                mma_bf16(acc[mt][nt], ah[mt], bh);
                mma_bf16(acc[mt][nt], al[mt], bh);
                mma_bf16(acc[mt][nt], ah[mt], bl);
            }
        }
        if (t + 1 < nT) {
            sts(buf ^ 1);
            __syncthreads();
            buf ^= 1;
        }
    }

#pragma unroll
    for (int mt = 0; mt < 2; mt++)
#pragma unroll
        for (int nt = 0; nt < 4; nt++)
#pragma unroll
            for (int half = 0; half < 2; half++) {
                int row = b * Sq + qt * 128 + wm * 32 + mt * 16 + g + half * 8;
                int ch  = h * 64 + wn * 32 + nt * 8 + 2 * tig;
                Abs[(size_t)row * 256 + (ch >> 1)] =
                    split2(acc[mt][nt][half*2], acc[mt][nt][half*2+1]);
            }
}

// ---------------- residual + LayerNorm (fp32 + split out) ----------------
__global__ void ln_add_kernel(const float* __restrict__ A, const float* __restrict__ Bv,
                              const float* __restrict__ sc, const float* __restrict__ bi,
                              float* __restrict__ out, uint2* __restrict__ outs)
{
    int r = blockIdx.x, tid = threadIdx.x;
    int c0 = tid * 4;
    const float* a  = A  + (size_t)r * Dm;
    const float* bq = Bv + (size_t)r * Dm;
    float4 a4 = *(const float4*)&a[c0];
    float4 b4 = *(const float4*)&bq[c0];
    float v[4] = {a4.x + b4.x, a4.y + b4.y, a4.z + b4.z, a4.w + b4.w};
    float s = v[0] + v[1] + v[2] + v[3];
    float s2 = v[0]*v[0] + v[1]*v[1] + v[2]*v[2] + v[3]*v[3];
    __shared__ float rs[4], rs2[4];
#pragma unroll
    for (int o = 16; o > 0; o >>= 1) {
        s  += __shfl_down_sync(0xffffffffu, s,  o);
        s2 += __shfl_down_sync(0xffffffffu, s2, o);
    }
    int w = tid >> 5, l = tid & 31;
    if (l == 0) { rs[w] = s; rs2[w] = s2; }
    __syncthreads();
    float ss  = rs[0] + rs[1] + rs[2] + rs[3];
    float ss2 = rs2[0] + rs2[1] + rs2[2] + rs2[3];
    float mean = ss / 512.f;
    float var  = ss2 / 512.f - mean * mean;
    float rstd = rsqrtf(var + 1e-5f);
    float4 sc4 = *(const float4*)&sc[c0];
    float4 bi4 = *(const float4*)&bi[c0];
    float o0 = (v[0] - mean) * rstd * sc4.x + bi4.x;
    float o1 = (v[1] - mean) * rstd * sc4.y + bi4.y;
    float o2 = (v[2] - mean) * rstd * sc4.z + bi4.z;
    float o3 = (v[3] - mean) * rstd * sc4.w + bi4.w;
    *(float4*)&out[(size_t)r * Dm + c0] = make_float4(o0, o1, o2, o3);
    size_t sb = (size_t)r * 256 + (c0 >> 1);
    outs[sb]     = split2(o0, o1);
    outs[sb + 1] = split2(o2, o3);
}

// ---------------- concat splits ----------------
__global__ void concat_kernel(const uint2* __restrict__ xs, const uint2* __restrict__ x0s,
                              uint2* __restrict__ Ccs)
{
    int r = blockIdx.x;
    int u = threadIdx.x;
    Ccs[(size_t)r * 512 + u]       = xs [(size_t)r * 256 + u];
    Ccs[(size_t)r * 512 + 256 + u] = x0s[(size_t)r * 256 + u];
}

// ---------------- host ----------------
static inline void gemmHL(const uint2* A, const uint2* W, int ldw, const float* bias,
                          float* C, int ldc, uint2* Chl, int ldch,
                          int M, int N, int K, int relu)
{
    dim3 grid((N + 63) / 64, M / 128);
    gemm_hl64<<<grid, 256>>>(A, W, ldw, bias, C, ldc, Chl, ldch, M, N, K, relu);
}

extern "C" void kernel_launch(void* const* d_in, const int* in_sizes, int n_in,
                              void* d_out, int out_size)
{
    const int*   c_data  = (const int*)  d_in[0];
    const int*   ca_data = (const int*)  d_in[1];
    const float* c_emb   = (const float*)d_in[2];
    const float* ca_emb  = (const float*)d_in[3];
    const float* Wk      = (const float*)d_in[4];
    const float* bk      = (const float*)d_in[5];
    const float* Wv      = (const float*)d_in[6];
    const float* bv      = (const float*)d_in[7];
    const float* Wo      = (const float*)d_in[8];
    const float* bo      = (const float*)d_in[9];
    const float* gammas  = (const float*)d_in[10];
    const float* ln1s    = (const float*)d_in[11];
    const float* ln1b    = (const float*)d_in[12];
    const float* W1      = (const float*)d_in[13];
    const float* b1      = (const float*)d_in[14];
    const float* W2      = (const float*)d_in[15];
    const float* b2      = (const float*)d_in[16];
    const float* ln2s    = (const float*)d_in[17];
    const float* ln2b    = (const float*)d_in[18];
    const float* oW0     = (const float*)d_in[19];
    const float* ob0     = (const float*)d_in[20];
    const float* oW1     = (const float*)d_in[21];
    const float* ob1     = (const float*)d_in[22];
    const float* oW2     = (const float*)d_in[23];
    const float* ob2     = (const float*)d_in[24];
    float* out = (float*)d_out;

    cudaFuncSetAttribute(score_tc, cudaFuncAttributeMaxDynamicSharedMemorySize, SCORE_SMEM);

    float *y, *x, *QV, *Ob, *T1, *Sb, *bqv;
    cudaGetSymbolAddress((void**)&y,  g_y);
    cudaGetSymbolAddress((void**)&x,  g_x);
    cudaGetSymbolAddress((void**)&QV, g_QV);
    cudaGetSymbolAddress((void**)&Ob, g_Ob);
    cudaGetSymbolAddress((void**)&T1, g_T1);
    cudaGetSymbolAddress((void**)&Sb, g_S);
    cudaGetSymbolAddress((void**)&bqv, g_bqv);
    uint2 *x0s, *ys, *xs, *T1s, *Abs, *Hfs, *Ccs, *M1s, *M2s, *QVs, *Ks, *Vts;
    uint2 *Wqvs, *Wos, *W1s, *W2s, *oW0s, *oW1s, *oW2s;
    cudaGetSymbolAddress((void**)&x0s, g_x0s);
    cudaGetSymbolAddress((void**)&ys,  g_ys);
    cudaGetSymbolAddress((void**)&xs,  g_xs);
    cudaGetSymbolAddress((void**)&T1s, g_T1s);
    cudaGetSymbolAddress((void**)&Abs, g_Abs);
    cudaGetSymbolAddress((void**)&Hfs, g_Hfs);
    cudaGetSymbolAddress((void**)&Ccs, g_Ccs);
    cudaGetSymbolAddress((void**)&M1s, g_M1s);
    cudaGetSymbolAddress((void**)&M2s, g_M2s);
    cudaGetSymbolAddress((void**)&QVs, g_QVs);
    cudaGetSymbolAddress((void**)&Ks,  g_Ks);
    cudaGetSymbolAddress((void**)&Vts, g_Vts);
    cudaGetSymbolAddress((void**)&Wqvs, g_Wqvs);
    cudaGetSymbolAddress((void**)&Wos,  g_Wos);
    cudaGetSymbolAddress((void**)&W1s,  g_W1s);
    cudaGetSymbolAddress((void**)&W2s,  g_W2s);
    cudaGetSymbolAddress((void**)&oW0s, g_oW0s);
    cudaGetSymbolAddress((void**)&oW1s, g_oW1s);
    cudaGetSymbolAddress((void**)&oW2s, g_oW2s);

    // ---- weight prep ----
    split_w<<<dim3(512,1,6), 256>>>(Wk, Wqvs, 512, 512, 1024, 0,   (size_t)512*512, (size_t)256*1024);
    split_w<<<dim3(512,1,6), 256>>>(Wv, Wqvs, 512, 512, 1024, 512, (size_t)512*512, (size_t)256*1024);
    split_w<<<dim3(512,1,6), 256>>>(Wo, Wos,  512, 512, 512,  0,   (size_t)512*512, (size_t)256*512);
    split_w<<<dim3(2048,1,6),256>>>(W1, W1s,  512, 2048, 2048,0,   (size_t)512*2048,(size_t)256*2048);
    split_w<<<dim3(2048,1,6),256>>>(W2, W2s,  2048,512,  512, 0,   (size_t)2048*512,(size_t)1024*512);
    split_w<<<dim3(1024,1,1),256>>>(oW0, oW0s, 1024, 512, 512, 0, 0, 0);
    split_w<<<dim3(1024,1,1),256>>>(oW1, oW1s, 512, 1024, 1024, 0, 0, 0);
    split_w<<<dim3(2000,1,1),256>>>(oW2, oW2s, 1024, 1000, 1000, 0, 0, 0);
    pack_bqv<<<24, 256>>>(bk, bv, bqv);

    embed_kernel<<<MTOK, 128>>>(c_data, ca_data, c_emb, ca_emb, y, x, x0s, ys, xs);

    for (int li = 0; li < 6; li++) {
        int strict, ap;
        float* qio; uint2* qios;
        const uint2* Bspl; int ldk;
        uint2* Wqv_i = Wqvs + (size_t)li * 256 * 1024;

        if (li < 2) {
            strict = 0; ap = 1; qio = y; qios = ys;
            gemmHL(x0s, Wqv_i, 1024, bk + li*512, nullptr, 0, Ks, 256, MTOK, 512, 512, 0);
            gemmHL(ys, Wqv_i, 1024, bqv + li*1024, QV, 1024, QVs, 512, MTOK, 1024, 512, 0);
            Bspl = Ks; ldk = 256;
        } else {
            int j = li - 2;
            qio = x; qios = xs;
            if ((j & 1) == 0) {
                strict = 0; ap = 0;
                gemmHL(xs, Wqv_i, 1024, bqv + li*1024, QV, 1024, QVs, 512, MTOK, 1024, 512, 0);
            } else {
                strict = 1; ap = 1;
                gemmHL(xs, Wqv_i, 1024, bk + li*512, nullptr, 0, QVs, 512, MTOK, 512, 512, 0);
                gemmHL(ys, Wqv_i + 512, 1024, bv + li*512, QV + 512, 1024, nullptr, 0, MTOK, 512, 512, 0);
            }
            Bspl = QVs; ldk = 512;
        }

        vtsplit<<<dim3(16, NBH), 256>>>(QV + 512, Vts);
        score_tc<<<dim3(4, 4, NBH), 512, SCORE_SMEM>>>(QVs, 512, Bspl, ldk, Sb);
        decay_softmax_warp<<<4096, 256>>>(Sb, gammas, li, strict);
        av_tc<<<dim3(4, NBH), 256>>>(Sb, Vts, Abs);

        gemmHL(Abs, Wos + (size_t)li * 256 * 512, 512, bo + li*512, Ob, 512, nullptr, 0, MTOK, 512, 512, 0);
        ln_add_kernel<<<MTOK, 128>>>(qio, Ob, ln1s + li*Dm, ln1b + li*Dm,
                                     ap ? T1 : qio, ap ? T1s : qios);
        if (ap) {
            gemmHL(T1s, W1s + (size_t)li * 256 * 2048, 2048, b1 + li*FF,
                   nullptr, 0, Hfs, 1024, MTOK, 2048, 512, 1);
            gemmHL(Hfs, W2s + (size_t)li * 1024 * 512, 512, b2 + li*512,
                   Ob, 512, nullptr, 0, MTOK, 512, 2048, 0);
            ln_add_kernel<<<MTOK, 128>>>(T1, Ob, ln2s + li*Dm, ln2b + li*Dm, qio, qios);
        }
    }

    concat_kernel<<<MTOK, 256>>>(xs, x0s, Ccs);
    gemmHL(Ccs, oW0s, 512,  ob0, nullptr, 0, M1s, 256, MTOK, 512,  1024, 1);
    gemmHL(M1s, oW1s, 1024, ob1, nullptr, 0, M2s, 512, MTOK, 1024, 512,  1);
    gemmHL(M2s, oW2s, 1000, ob2, out, 1000, nullptr, 0, MTOK, 1000, 1024, 0);
}

// round 16
// speedup vs baseline: 1.0221x; 1.0221x over previous
#include <cuda_runtime.h>
#include <cuda_bf16.h>
#include <math.h>
#include <stdint.h>

#define Bsz 8
#define Sq  512
#define Dm  512
#define Hh  8
#define DK  64
#define FF  2048
#define MTOK (Bsz*Sq)   // 4096
#define NCPT 1000
#define NBH (Bsz*Hh)    // 64

// ---------------- scratch (device globals; no allocation) ----------------
__device__ float g_y [MTOK*Dm];
__device__ float g_x [MTOK*Dm];
__device__ float g_QV[MTOK*1024];
__device__ float g_Ob[MTOK*Dm];
__device__ float g_T1[MTOK*Dm];
__device__ float g_S [NBH*Sq*Sq];          // 64 MB raw scores
__device__ uint2 g_Ss[NBH*Sq*256];         // 64 MB split attn weights (pairs)
__device__ float g_bqv[6*1024];
// split (hi/lo bf16 pair-packed) activations: uint2 per k-pair
__device__ uint2 g_x0s[MTOK*256];
__device__ uint2 g_ys [MTOK*256];
__device__ uint2 g_xs [MTOK*256];
__device__ uint2 g_T1s[MTOK*256];
__device__ uint2 g_Abs[MTOK*256];
__device__ uint2 g_Hfs[MTOK*1024];
__device__ uint2 g_Ccs[MTOK*512];
__device__ uint2 g_M1s[MTOK*256];
__device__ uint2 g_M2s[MTOK*512];
__device__ uint2 g_QVs[MTOK*512];          // split Q|V (Q part used)
__device__ uint2 g_Ks [MTOK*256];          // split K (layers 0-1)
__device__ uint2 g_Vts[NBH*64*256];        // split V^T per (b,h): [d][seq-pair]
// split weights (k-pair packed [K/2][N])
__device__ uint2 g_Wqvs[6*256*1024];
__device__ uint2 g_Wos [6*256*512];
__device__ uint2 g_W1s [6*256*2048];
__device__ uint2 g_W2s [6*1024*512];
__device__ uint2 g_oW0s[512*512];
__device__ uint2 g_oW1s[256*1024];
__device__ uint2 g_oW2s[512*1000];

// ---------------- split helper ----------------
__device__ __forceinline__ uint2 split2(float v0, float v1) {
    __nv_bfloat16 h0 = __float2bfloat16(v0);
    __nv_bfloat16 h1 = __float2bfloat16(v1);
    float r0 = v0 - __bfloat162float(h0);
    float r1 = v1 - __bfloat162float(h1);
    __nv_bfloat162 hh; hh.x = h0; hh.y = h1;
    __nv_bfloat162 ll = __floats2bfloat162_rn(r0, r1);
    return make_uint2(*(uint32_t*)&hh, *(uint32_t*)&ll);
}
__device__ __forceinline__ void mma_bf16(float* c, const uint32_t* a, const uint32_t* b) {
    asm volatile(
        "mma.sync.aligned.m16n8k16.row.col.f32.bf16.bf16.f32 "
        "{%0,%1,%2,%3}, {%4,%5,%6,%7}, {%8,%9}, {%0,%1,%2,%3};"
        : "+f"(c[0]), "+f"(c[1]), "+f"(c[2]), "+f"(c[3])
        : "r"(a[0]), "r"(a[1]), "r"(a[2]), "r"(a[3]), "r"(b[0]), "r"(b[1]));
}

// ---------------- weight split: W[K][N] fp32 -> out[K/2][ldo] uint2 ----------
__global__ void split_w(const float* __restrict__ W, uint2* __restrict__ out,
                        int K, int N, int ldo, int colOff,
                        size_t inStride, size_t outStride)
{
    int z = blockIdx.z;
    const float* Wz = W + (size_t)z * inStride;
    uint2* oz = out + (size_t)z * outStride + colOff;
    int KP = K >> 1;
    int total = KP * N;
    for (int idx = blockIdx.x * blockDim.x + threadIdx.x; idx < total;
         idx += gridDim.x * blockDim.x) {
        int kp = idx / N, n = idx - kp * N;
        float v0 = Wz[(size_t)(2 * kp) * N + n];
        float v1 = Wz[(size_t)(2 * kp + 1) * N + n];
        oz[(size_t)kp * ldo + n] = split2(v0, v1);
    }
}

__global__ void pack_bqv(const float* __restrict__ bk, const float* __restrict__ bv,
                         float* __restrict__ bqv)
{
    int i = blockIdx.x * blockDim.x + threadIdx.x;
    if (i >= 6 * 1024) return;
    int li = i >> 10, j = i & 1023;
    bqv[i] = (j < 512) ? bk[li * 512 + j] : bv[li * 512 + j - 512];
}

// ---------------- embed ----------------
__global__ void embed_kernel(const int* __restrict__ c_data, const int* __restrict__ ca_data,
                             const float* __restrict__ c_emb, const float* __restrict__ ca_emb,
                             float* __restrict__ y, float* __restrict__ x,
                             uint2* __restrict__ x0s, uint2* __restrict__ ys, uint2* __restrict__ xs)
{
    int r = blockIdx.x;
    int c = c_data[r];
    int resp = (ca_data[r] - c) / NCPT;
    const float* er = c_emb + (size_t)c * Dm;
    const float* ar = ca_emb + (size_t)resp * Dm;
    int j = threadIdx.x * 4;
    float4 e4 = *(const float4*)(er + j);
    float4 a4 = *(const float4*)(ar + j);
    float y0 = e4.x + a4.x, y1 = e4.y + a4.y, y2 = e4.z + a4.z, y3 = e4.w + a4.w;
    *(float4*)&x[(size_t)r*Dm + j] = e4;
    *(float4*)&y[(size_t)r*Dm + j] = make_float4(y0, y1, y2, y3);
    size_t sb = (size_t)r * 256 + (j >> 1);
    uint2 s0 = split2(e4.x, e4.y), s1 = split2(e4.z, e4.w);
    x0s[sb] = s0; x0s[sb + 1] = s1;
    xs [sb] = s0; xs [sb + 1] = s1;
    ys [sb] = split2(y0, y1); ys[sb + 1] = split2(y2, y3);
}

// ---------------- bf16x3 tensor-core GEMM, 128x64 tile, 2 CTAs/SM -----------
#define GP 138

__global__ __launch_bounds__(256, 2)
void gemm_hl64(const uint2* __restrict__ Ahl, const uint2* __restrict__ Whl, int ldw,
               const float* __restrict__ bias, float* __restrict__ C, int ldc,
               uint2* __restrict__ Chl, int ldch,
               int M, int N, int K, int relu)
{
    __shared__ uint2 As[2][8][GP];
    __shared__ uint2 Bs[2][8][66];

    int tid = threadIdx.x;
    int row0 = blockIdx.y * 128, col0 = blockIdx.x * 64;
    int warp = tid >> 5, lane = tid & 31;
    int wm = warp & 3, wn = warp >> 2;      // 4x2 warps, 32x32 tiles
    int g = lane >> 2, tig = lane & 3;

    int arow = tid >> 1, aks = tid & 1;
    int bn = tid & 63, bg = tid >> 6;       // bg: 0..3
    int KP = K >> 1;
    const uint2* Ap = Ahl + (size_t)(row0 + arow) * KP + aks * 4;
    int bcg = col0 + bn;
    bool bok = bcg < N;

    float acc[2][4][4];
#pragma unroll
    for (int i = 0; i < 2; i++)
#pragma unroll
        for (int j = 0; j < 4; j++)
#pragma unroll
            for (int q = 0; q < 4; q++) acc[i][j][q] = 0.f;

    uint2 arv[4], brv[2];
    int T = K >> 4;

    auto ldg = [&](int t) {
        const uint2* p = Ap + t * 8;
        uint4 u0 = *(const uint4*)p;
        uint4 u1 = *(const uint4*)(p + 2);
        arv[0] = make_uint2(u0.x, u0.y); arv[1] = make_uint2(u0.z, u0.w);
        arv[2] = make_uint2(u1.x, u1.y); arv[3] = make_uint2(u1.z, u1.w);
        if (bok) {
            brv[0] = Whl[(size_t)(t * 8 + bg)     * ldw + bcg];
            brv[1] = Whl[(size_t)(t * 8 + bg + 4) * ldw + bcg];
        } else {
            brv[0] = make_uint2(0, 0); brv[1] = make_uint2(0, 0);
        }
    };
    auto sts = [&](int bf) {
#pragma unroll
        for (int jj = 0; jj < 4; jj++) As[bf][jj * 2 + aks][arow] = arv[jj];
        Bs[bf][bg * 2    ][bn] = brv[0];
        Bs[bf][bg * 2 + 1][bn] = brv[1];
    };

    ldg(0); sts(0);
    __syncthreads();

    int buf = 0;
    for (int t = 0; t < T; t++) {
        if (t + 1 < T) ldg(t + 1);
        uint32_t ah[2][4], al[2][4];
#pragma unroll
        for (int mt = 0; mt < 2; mt++) {
            int r = wm * 32 + mt * 16 + g;
            uint2 ua = As[buf][2*tig    ][r];
            uint2 ub = As[buf][2*tig    ][r + 8];
            uint2 uc = As[buf][2*tig + 1][r];
            uint2 ud = As[buf][2*tig + 1][r + 8];
            ah[mt][0]=ua.x; ah[mt][1]=ub.x; ah[mt][2]=uc.x; ah[mt][3]=ud.x;
            al[mt][0]=ua.y; al[mt][1]=ub.y; al[mt][2]=uc.y; al[mt][3]=ud.y;
        }
#pragma unroll
        for (int nt = 0; nt < 4; nt++) {
            int n0 = wn * 32 + nt * 8 + g;
            uint2 u0 = Bs[buf][2*tig    ][n0];
            uint2 u1 = Bs[buf][2*tig + 1][n0];
            uint32_t bh[2] = {u0.x, u1.x};
            uint32_t bl[2] = {u0.y, u1.y};
#pragma unroll
            for (int mt = 0; mt < 2; mt++) {
                mma_bf16(acc[mt][nt], ah[mt], bh);
                mma_bf16(acc[mt][nt], al[mt], bh);
                mma_bf16(acc[mt][nt], ah[mt], bl);
            }
        }
        if (t + 1 < T) {
            sts(buf ^ 1);
            __syncthreads();
            buf ^= 1;
        }
    }

#pragma unroll
    for (int mt = 0; mt < 2; mt++) {
        int rbase = row0 + wm * 32 + mt * 16;
#pragma unroll
        for (int nt = 0; nt < 4; nt++) {
            int cb = col0 + wn * 32 + nt * 8 + 2 * tig;
            float b0 = (cb < N) ? bias[cb] : 0.f;
            float b1 = (cb + 1 < N) ? bias[cb + 1] : 0.f;
#pragma unroll
            for (int half = 0; half < 2; half++) {
                int r = rbase + g + half * 8;
                float v0 = acc[mt][nt][half * 2 + 0] + b0;
                float v1 = acc[mt][nt][half * 2 + 1] + b1;
                if (relu) { v0 = fmaxf(v0, 0.f); v1 = fmaxf(v1, 0.f); }
                if (C) {
                    if (cb < N)     C[(size_t)r * ldc + cb]     = v0;
                    if (cb + 1 < N) C[(size_t)r * ldc + cb + 1] = v1;
                }
                if (Chl && cb + 1 < N)
                    Chl[(size_t)r * ldch + (cb >> 1)] = split2(v0, v1);
            }
        }
    }
}

// ---------------- V transpose + split: Vt[z][d][seq-pair] -------------------
__global__ void vtsplit(const float* __restrict__ V, uint2* __restrict__ Vts)
{
    __shared__ float t[32][65];
    int z = blockIdx.y, b = z >> 3, h = z & 7;
    int s0 = blockIdx.x * 32;
    int tid = threadIdx.x;
    {
        int i = tid >> 3, fj = tid & 7;
        const float* src = V + (size_t)(b * Sq + s0 + i) * 1024 + h * 64 + fj * 8;
        float4 v0 = *(const float4*)src;
        float4 v1 = *(const float4*)(src + 4);
        t[i][fj*8+0] = v0.x; t[i][fj*8+1] = v0.y; t[i][fj*8+2] = v0.z; t[i][fj*8+3] = v0.w;
        t[i][fj*8+4] = v1.x; t[i][fj*8+5] = v1.y; t[i][fj*8+6] = v1.z; t[i][fj*8+7] = v1.w;
    }
    __syncthreads();
    int d = tid >> 2, q = tid & 3;
    uint2* dst = Vts + ((size_t)z * 64 + d) * 256 + (s0 >> 1);
#pragma unroll
    for (int j = 0; j < 4; j++) {
        int kp = q * 4 + j;
        dst[kp] = split2(t[2*kp][d], t[2*kp+1][d]);
    }
}

// ---------------- attention part 1: scores via tensor cores -----------------
#define SGP 130
#define SCORE_SMEM (2*4*8*SGP*(int)sizeof(uint2))
__global__ __launch_bounds__(512, 2)
void score_tc(const uint2* __restrict__ Qs, int ldq,
              const uint2* __restrict__ Ks, int ldk,
              float* __restrict__ S)
{
    int kt = blockIdx.x, qt = blockIdx.y;
    if (kt > qt) return;
    int z = blockIdx.z, b = z >> 3, h = z & 7;
    extern __shared__ uint2 sm[];
    uint2 (*As)[8][SGP] = (uint2(*)[8][SGP])sm;
    uint2 (*Bs)[8][SGP] = (uint2(*)[8][SGP])(sm + 4*8*SGP);

    int tid = threadIdx.x;
    {
        int r = tid >> 2, quarter = tid & 3;
        const uint2* qa = Qs + (size_t)(b*Sq + qt*128 + r) * ldq + h*32 + quarter*8;
        const uint2* ka = Ks + (size_t)(b*Sq + kt*128 + r) * ldk + h*32 + quarter*8;
#pragma unroll
        for (int j = 0; j < 4; j++) {
            uint4 uq = *(const uint4*)(qa + 2*j);
            uint4 uk = *(const uint4*)(ka + 2*j);
            int m0 = 2*j, m1 = 2*j + 1;
            int sl0 = (m0 & 3)*2 + (m0 >> 2);
            int sl1 = (m1 & 3)*2 + (m1 >> 2);
            As[quarter][sl0][r] = make_uint2(uq.x, uq.y);
            As[quarter][sl1][r] = make_uint2(uq.z, uq.w);
            Bs[quarter][sl0][r] = make_uint2(uk.x, uk.y);
            Bs[quarter][sl1][r] = make_uint2(uk.z, uk.w);
        }
    }
    __syncthreads();

    int warp = tid >> 5, lane = tid & 31;
    int wm = warp & 3, wn = warp >> 2;
    int g = lane >> 2, tig = lane & 3;
    float acc[2][4][4];
#pragma unroll
    for (int i = 0; i < 2; i++)
#pragma unroll
        for (int j = 0; j < 4; j++)
#pragma unroll
            for (int q = 0; q < 4; q++) acc[i][j][q] = 0.f;

#pragma unroll
    for (int c = 0; c < 4; c++) {
        uint32_t ah[2][4], al[2][4];
#pragma unroll
        for (int mt = 0; mt < 2; mt++) {
            int r = wm * 32 + mt * 16 + g;
            uint2 ua = As[c][2*tig    ][r];
            uint2 ub = As[c][2*tig    ][r + 8];
            uint2 uc = As[c][2*tig + 1][r];
            uint2 ud = As[c][2*tig + 1][r + 8];
            ah[mt][0]=ua.x; ah[mt][1]=ub.x; ah[mt][2]=uc.x; ah[mt][3]=ud.x;
            al[mt][0]=ua.y; al[mt][1]=ub.y; al[mt][2]=uc.y; al[mt][3]=ud.y;
        }
#pragma unroll
        for (int nt = 0; nt < 4; nt++) {
            int n0 = wn * 32 + nt * 8 + g;
            uint2 u0 = Bs[c][2*tig    ][n0];
            uint2 u1 = Bs[c][2*tig + 1][n0];
            uint32_t bh[2] = {u0.x, u1.x};
            uint32_t bl[2] = {u0.y, u1.y};
#pragma unroll
            for (int mt = 0; mt < 2; mt++) {
                mma_bf16(acc[mt][nt], ah[mt], bh);
                mma_bf16(acc[mt][nt], al[mt], bh);
                mma_bf16(acc[mt][nt], ah[mt], bl);
            }
        }
    }

    float* Sbase = S + ((size_t)z * Sq + qt * 128) * Sq + kt * 128;
#pragma unroll
    for (int mt = 0; mt < 2; mt++)
#pragma unroll
        for (int nt = 0; nt < 4; nt++)
#pragma unroll
            for (int half = 0; half < 2; half++) {
                int row = wm * 32 + mt * 16 + g + half * 8;
                int col = wn * 32 + nt * 8 + 2 * tig;
                float2 v = make_float2(acc[mt][nt][half*2] * 0.125f,
                                       acc[mt][nt][half*2+1] * 0.125f);
                *(float2*)&Sbase[(size_t)row * Sq + col] = v;
            }
}

// ---------------- attention part 2: warp-per-row softmax/decay --------------
// reads fp32 scores from S, writes SPLIT bf16 pair weights into Ss
__global__ __launch_bounds__(256)
void decay_softmax_warp(const float* __restrict__ S, uint2* __restrict__ Ss,
                        const float* __restrict__ gammas,
                        int layer, int strict)
{
    int lane = threadIdx.x & 31;
    int gw = blockIdx.x * 8 + (threadIdx.x >> 5);   // global warp id, 32768 total
    int z = gw >> 9, i = gw & 511;
    int h = z & 7;
    const float* row = S + ((size_t)z * Sq + i) * Sq;
    uint2* orow = Ss + ((size_t)z * Sq + i) * 256;
    int kmax = i - strict;
    int kend = ((i >> 7) + 1) * 128;     // av_tc reads only tiles kt <= qt
    int base = lane * 16;
    int pb = lane * 8;                    // pair base
    if (kmax < 0) {
        if (base < kend) {
            uint4 zz = make_uint4(0, 0, 0, 0);
#pragma unroll
            for (int j = 0; j < 4; j++)
                *(uint4*)&orow[pb + 2 * j] = zz;
        }
        return;
    }

    float v[16];
#pragma unroll
    for (int j = 0; j < 4; j++) {
        int k = base + 4 * j;
        if (k + 3 <= kmax) {
            float4 f = *(const float4*)&row[k];
            v[4*j] = f.x; v[4*j+1] = f.y; v[4*j+2] = f.z; v[4*j+3] = f.w;
        } else {
#pragma unroll
            for (int e = 0; e < 4; e++)
                v[4*j+e] = (k + e <= kmax) ? row[k + e] : 0.f;
        }
    }

    float lm = -3e38f;
#pragma unroll
    for (int j = 0; j < 16; j++) if (base + j <= kmax) lm = fmaxf(lm, v[j]);
#pragma unroll
    for (int o = 16; o; o >>= 1) lm = fmaxf(lm, __shfl_xor_sync(~0u, lm, o));
    float m1 = lm;

    float p[16];
    float ls = 0.f;
#pragma unroll
    for (int j = 0; j < 16; j++) {
        p[j] = (base + j <= kmax) ? expf(v[j] - m1) : 0.f;
        ls += p[j];
    }
    float ws = ls;
#pragma unroll
    for (int o = 16; o; o >>= 1) ws += __shfl_xor_sync(~0u, ws, o);
    float inv1 = 1.f / ws;
#pragma unroll
    for (int j = 0; j < 16; j++) p[j] *= inv1;

    float cum[16];
    float run = 0.f;
#pragma unroll
    for (int j = 0; j < 16; j++) { run += p[j]; cum[j] = run; }
    float t = run;
#pragma unroll
    for (int o = 1; o < 32; o <<= 1) {
        float tt = __shfl_up_sync(~0u, t, o);
        if (lane >= o) t += tt;
    }
    float excl  = t - run;
    float total = __shfl_sync(~0u, t, 31);

    float gm = gammas[layer * Hh + h];
    float sp = (gm > 20.f) ? gm : log1pf(expf(gm));
    float gamma = -sp;

#pragma unroll
    for (int j = 0; j < 16; j++) {
        float suf  = total - (excl + cum[j]);
        float pos  = (float)(i - (base + j));
        float dist = sqrtf(fmaxf(suf * pos, 0.f));
        float te   = fminf(fmaxf(expf(dist * gamma), 1e-5f), 1e5f);
        v[j] = v[j] * te;
    }

    lm = -3e38f;
#pragma unroll
    for (int j = 0; j < 16; j++) if (base + j <= kmax) lm = fmaxf(lm, v[j]);
#pragma unroll
    for (int o = 16; o; o >>= 1) lm = fmaxf(lm, __shfl_xor_sync(~0u, lm, o));
    float m2 = lm;

    ls = 0.f;
#pragma unroll
    for (int j = 0; j < 16; j++) {
        p[j] = (base + j <= kmax) ? expf(v[j] - m2) : 0.f;
        ls += p[j];
    }
    ws = ls;
#pragma unroll
    for (int o = 16; o; o >>= 1) ws += __shfl_xor_sync(~0u, ws, o);
    float inv2 = 1.f / ws;

    if (base < kend) {
#pragma unroll
        for (int j = 0; j < 4; j++) {
            uint2 a = split2(p[4*j]     * inv2, p[4*j + 1] * inv2);
            uint2 bu = split2(p[4*j + 2] * inv2, p[4*j + 3] * inv2);
            *(uint4*)&orow[pb + 2 * j] = make_uint4(a.x, a.y, bu.x, bu.y);
        }
    }
}

// ---------------- attention part 3: O = P @ V via tensor cores --------------
// P pre-split: Ss[row][pair] uint2
__global__ __launch_bounds__(256, 2)
void av_tc(const uint2* __restrict__ Ss, const uint2* __restrict__ Vts,
           uint2* __restrict__ Abs)
{
    __shared__ uint2 As[2][8][130];
    __shared__ uint2 Bs[2][8][66];
    int qt = blockIdx.x, z = blockIdx.y, b = z >> 3, h = z & 7;
    int tid = threadIdx.x;
    int warp = tid >> 5, lane = tid & 31;
    int wm = warp & 3, wn = warp >> 2;     // 4x2, 32q x 32d
    int g = lane >> 2, tig = lane & 3;

    int ar = tid >> 1, ahalf = tid & 1;
    const uint2* Sbase = Ss + ((size_t)z * Sq + qt * 128 + ar) * 256 + ahalf * 4;
    int bd = tid & 63, bpr = tid >> 6;
    const uint2* Vbase = Vts + ((size_t)z * 64 + bd) * 256 + bpr * 2;

    int nT = (qt + 1) * 8;
    uint2 fa[4]; uint4 bu;
    auto ldg = [&](int t) {
        uint4 u0 = *(const uint4*)(Sbase + t * 8);
        uint4 u1 = *(const uint4*)(Sbase + t * 8 + 2);
        fa[0] = make_uint2(u0.x, u0.y); fa[1] = make_uint2(u0.z, u0.w);
        fa[2] = make_uint2(u1.x, u1.y); fa[3] = make_uint2(u1.z, u1.w);
        bu = *(const uint4*)(Vbase + (size_t)t * 8);
    };
    auto sts = [&](int bf) {
#pragma unroll
        for (int j = 0; j < 4; j++)
            As[bf][j * 2 + ahalf][ar] = fa[j];
        int m0 = bpr * 2, m1 = bpr * 2 + 1;
        Bs[bf][(m0 & 3)*2 + (m0 >> 2)][bd] = make_uint2(bu.x, bu.y);
        Bs[bf][(m1 & 3)*2 + (m1 >> 2)][bd] = make_uint2(bu.z, bu.w);
    };

    float acc[2][4][4];
#pragma unroll
    for (int i = 0; i < 2; i++)
#pragma unroll
        for (int j = 0; j < 4; j++)
#pragma unroll
            for (int q = 0; q < 4; q++) acc[i][j][q] = 0.f;

    ldg(0); sts(0);
    __syncthreads();
    int buf = 0;
    for (int t = 0; t < nT; t++) {
        if (t + 1 < nT) ldg(t + 1);
        uint32_t ah[2][4], al[2][4];
#pragma unroll
        for (int mt = 0; mt < 2; mt++) {
            int r = wm * 32 + mt * 16 + g;
            uint2 ua = As[buf][2*tig    ][r];
            uint2 ub = As[buf][2*tig    ][r + 8];
            uint2 uc = As[buf][2*tig + 1][r];
            uint2 ud = As[buf][2*tig + 1][r + 8];
            ah[mt][0]=ua.x; ah[mt][1]=ub.x; ah[mt][2]=uc.x; ah[mt][3]=ud.x;
            al[mt][0]=ua.y; al[mt][1]=ub.y; al[mt][2]=uc.y; al[mt][3]=ud.y;
        }
#pragma unroll
        for (int nt = 0; nt < 4; nt++) {
            int n0 = wn * 32 + nt * 8 + g;
            uint2 u0 = Bs[buf][2*tig    ][n0];
            uint2 u1 = Bs[buf][2*tig + 1][n0];
            uint32_t bh[2] = {u0.x, u1.x};
            uint32_t bl[2] = {u0.y, u1.y};
#pragma unroll
            for (int mt = 0; mt < 2; mt++) {
                mma_bf16(acc[mt][nt], ah[mt], bh);
                mma_bf16(acc[mt][nt], al[mt], bh);
                mma_bf16(acc[mt][nt], ah[mt], bl);
            }
        }
        if (t + 1 < nT) {
            sts(buf ^ 1);
            __syncthreads();
            buf ^= 1;
        }
    }

#pragma unroll
    for (int mt = 0; mt < 2; mt++)
#pragma unroll
        for (int nt = 0; nt < 4; nt++)
#pragma unroll
            for (int half = 0; half < 2; half++) {
                int row = b * Sq + qt * 128 + wm * 32 + mt * 16 + g + half * 8;
                int ch  = h * 64 + wn * 32 + nt * 8 + 2 * tig;
                Abs[(size_t)row * 256 + (ch >> 1)] =
                    split2(acc[mt][nt][half*2], acc[mt][nt][half*2+1]);
            }
}

// ---------------- residual + LayerNorm (fp32 + split out) ----------------
__global__ void ln_add_kernel(const float* __restrict__ A, const float* __restrict__ Bv,
                              const float* __restrict__ sc, const float* __restrict__ bi,
                              float* __restrict__ out, uint2* __restrict__ outs)
{
    int r = blockIdx.x, tid = threadIdx.x;
    int c0 = tid * 4;
    const float* a  = A  + (size_t)r * Dm;
    const float* bq = Bv + (size_t)r * Dm;
    float4 a4 = *(const float4*)&a[c0];
    float4 b4 = *(const float4*)&bq[c0];
    float v[4] = {a4.x + b4.x, a4.y + b4.y, a4.z + b4.z, a4.w + b4.w};
    float s = v[0] + v[1] + v[2] + v[3];
    float s2 = v[0]*v[0] + v[1]*v[1] + v[2]*v[2] + v[3]*v[3];
    __shared__ float rs[4], rs2[4];
#pragma unroll
    for (int o = 16; o > 0; o >>= 1) {
        s  += __shfl_down_sync(0xffffffffu, s,  o);
        s2 += __shfl_down_sync(0xffffffffu, s2, o);
    }
    int w = tid >> 5, l = tid & 31;
    if (l == 0) { rs[w] = s; rs2[w] = s2; }
    __syncthreads();
    float ss  = rs[0] + rs[1] + rs[2] + rs[3];
    float ss2 = rs2[0] + rs2[1] + rs2[2] + rs2[3];
    float mean = ss / 512.f;
    float var  = ss2 / 512.f - mean * mean;
    float rstd = rsqrtf(var + 1e-5f);
    float4 sc4 = *(const float4*)&sc[c0];
    float4 bi4 = *(const float4*)&bi[c0];
    float o0 = (v[0] - mean) * rstd * sc4.x + bi4.x;
    float o1 = (v[1] - mean) * rstd * sc4.y + bi4.y;
    float o2 = (v[2] - mean) * rstd * sc4.z + bi4.z;
    float o3 = (v[3] - mean) * rstd * sc4.w + bi4.w;
    *(float4*)&out[(size_t)r * Dm + c0] = make_float4(o0, o1, o2, o3);
    size_t sb = (size_t)r * 256 + (c0 >> 1);
    outs[sb]     = split2(o0, o1);
    outs[sb + 1] = split2(o2, o3);
}

// ---------------- concat splits ----------------
__global__ void concat_kernel(const uint2* __restrict__ xs, const uint2* __restrict__ x0s,
                              uint2* __restrict__ Ccs)
{
    int r = blockIdx.x;
    int u = threadIdx.x;
    Ccs[(size_t)r * 512 + u]       = xs [(size_t)r * 256 + u];
    Ccs[(size_t)r * 512 + 256 + u] = x0s[(size_t)r * 256 + u];
}

// ---------------- host ----------------
static inline void gemmHL(const uint2* A, const uint2* W, int ldw, const float* bias,
                          float* C, int ldc, uint2* Chl, int ldch,
                          int M, int N, int K, int relu)
{
    dim3 grid((N + 63) / 64, M / 128);
    gemm_hl64<<<grid, 256>>>(A, W, ldw, bias, C, ldc, Chl, ldch, M, N, K, relu);
}

extern "C" void kernel_launch(void* const* d_in, const int* in_sizes, int n_in,
                              void* d_out, int out_size)
{
    const int*   c_data  = (const int*)  d_in[0];
    const int*   ca_data = (const int*)  d_in[1];
    const float* c_emb   = (const float*)d_in[2];
    const float* ca_emb  = (const float*)d_in[3];
    const float* Wk      = (const float*)d_in[4];
    const float* bk      = (const float*)d_in[5];
    const float* Wv      = (const float*)d_in[6];
    const float* bv      = (const float*)d_in[7];
    const float* Wo      = (const float*)d_in[8];
    const float* bo      = (const float*)d_in[9];
    const float* gammas  = (const float*)d_in[10];
    const float* ln1s    = (const float*)d_in[11];
    const float* ln1b    = (const float*)d_in[12];
    const float* W1      = (const float*)d_in[13];
    const float* b1      = (const float*)d_in[14];
    const float* W2      = (const float*)d_in[15];
    const float* b2      = (const float*)d_in[16];
    const float* ln2s    = (const float*)d_in[17];
    const float* ln2b    = (const float*)d_in[18];
    const float* oW0     = (const float*)d_in[19];
    const float* ob0     = (const float*)d_in[20];
    const float* oW1     = (const float*)d_in[21];
    const float* ob1     = (const float*)d_in[22];
    const float* oW2     = (const float*)d_in[23];
    const float* ob2     = (const float*)d_in[24];
    float* out = (float*)d_out;

    cudaFuncSetAttribute(score_tc, cudaFuncAttributeMaxDynamicSharedMemorySize, SCORE_SMEM);

    float *y, *x, *QV, *Ob, *T1, *Sb, *bqv;
    cudaGetSymbolAddress((void**)&y,  g_y);
    cudaGetSymbolAddress((void**)&x,  g_x);
    cudaGetSymbolAddress((void**)&QV, g_QV);
    cudaGetSymbolAddress((void**)&Ob, g_Ob);
    cudaGetSymbolAddress((void**)&T1, g_T1);
    cudaGetSymbolAddress((void**)&Sb, g_S);
    cudaGetSymbolAddress((void**)&bqv, g_bqv);
    uint2 *Ssb, *x0s, *ys, *xs, *T1s, *Abs, *Hfs, *Ccs, *M1s, *M2s, *QVs, *Ks, *Vts;
    uint2 *Wqvs, *Wos, *W1s, *W2s, *oW0s, *oW1s, *oW2s;
    cudaGetSymbolAddress((void**)&Ssb, g_Ss);
    cudaGetSymbolAddress((void**)&x0s, g_x0s);
    cudaGetSymbolAddress((void**)&ys,  g_ys);
    cudaGetSymbolAddress((void**)&xs,  g_xs);
    cudaGetSymbolAddress((void**)&T1s, g_T1s);
    cudaGetSymbolAddress((void**)&Abs, g_Abs);
    cudaGetSymbolAddress((void**)&Hfs, g_Hfs);
    cudaGetSymbolAddress((void**)&Ccs, g_Ccs);
    cudaGetSymbolAddress((void**)&M1s, g_M1s);
    cudaGetSymbolAddress((void**)&M2s, g_M2s);
    cudaGetSymbolAddress((void**)&QVs, g_QVs);
    cudaGetSymbolAddress((void**)&Ks,  g_Ks);
    cudaGetSymbolAddress((void**)&Vts, g_Vts);
    cudaGetSymbolAddress((void**)&Wqvs, g_Wqvs);
    cudaGetSymbolAddress((void**)&Wos,  g_Wos);
    cudaGetSymbolAddress((void**)&W1s,  g_W1s);
    cudaGetSymbolAddress((void**)&W2s,  g_W2s);
    cudaGetSymbolAddress((void**)&oW0s, g_oW0s);
    cudaGetSymbolAddress((void**)&oW1s, g_oW1s);
    cudaGetSymbolAddress((void**)&oW2s, g_oW2s);

    // ---- weight prep ----
    split_w<<<dim3(512,1,6), 256>>>(Wk, Wqvs, 512, 512, 1024, 0,   (size_t)512*512, (size_t)256*1024);
    split_w<<<dim3(512,1,6), 256>>>(Wv, Wqvs, 512, 512, 1024, 512, (size_t)512*512, (size_t)256*1024);
    split_w<<<dim3(512,1,6), 256>>>(Wo, Wos,  512, 512, 512,  0,   (size_t)512*512, (size_t)256*512);
    split_w<<<dim3(2048,1,6),256>>>(W1, W1s,  512, 2048, 2048,0,   (size_t)512*2048,(size_t)256*2048);
    split_w<<<dim3(2048,1,6),256>>>(W2, W2s,  2048,512,  512, 0,   (size_t)2048*512,(size_t)1024*512);
    split_w<<<dim3(1024,1,1),256>>>(oW0, oW0s, 1024, 512, 512, 0, 0, 0);
    split_w<<<dim3(1024,1,1),256>>>(oW1, oW1s, 512, 1024, 1024, 0, 0, 0);
    split_w<<<dim3(2000,1,1),256>>>(oW2, oW2s, 1024, 1000, 1000, 0, 0, 0);
    pack_bqv<<<24, 256>>>(bk, bv, bqv);

    embed_kernel<<<MTOK, 128>>>(c_data, ca_data, c_emb, ca_emb, y, x, x0s, ys, xs);

    for (int li = 0; li < 6; li++) {
        int strict, ap;
        float* qio; uint2* qios;
        const uint2* Bspl; int ldk;
        uint2* Wqv_i = Wqvs + (size_t)li * 256 * 1024;

        if (li < 2) {
            strict = 0; ap = 1; qio = y; qios = ys;
            gemmHL(x0s, Wqv_i, 1024, bk + li*512, nullptr, 0, Ks, 256, MTOK, 512, 512, 0);
            gemmHL(ys, Wqv_i, 1024, bqv + li*1024, QV, 1024, QVs, 512, MTOK, 1024, 512, 0);
            Bspl = Ks; ldk = 256;
        } else {
            int j = li - 2;
            qio = x; qios = xs;
            if ((j & 1) == 0) {
                strict = 0; ap = 0;
                gemmHL(xs, Wqv_i, 1024, bqv + li*1024, QV, 1024, QVs, 512, MTOK, 1024, 512, 0);
            } else {
                strict = 1; ap = 1;
                gemmHL(xs, Wqv_i, 1024, bk + li*512, nullptr, 0, QVs, 512, MTOK, 512, 512, 0);
                gemmHL(ys, Wqv_i + 512, 1024, bv + li*512, QV + 512, 1024, nullptr, 0, MTOK, 512, 512, 0);
            }
            Bspl = QVs; ldk = 512;
        }

        vtsplit<<<dim3(16, NBH), 256>>>(QV + 512, Vts);
        score_tc<<<dim3(4, 4, NBH), 512, SCORE_SMEM>>>(QVs, 512, Bspl, ldk, Sb);
        decay_softmax_warp<<<4096, 256>>>(Sb, Ssb, gammas, li, strict);
        av_tc<<<dim3(4, NBH), 256>>>(Ssb, Vts, Abs);

        gemmHL(Abs, Wos + (size_t)li * 256 * 512, 512, bo + li*512, Ob, 512, nullptr, 0, MTOK, 512, 512, 0);
        ln_add_kernel<<<MTOK, 128>>>(qio, Ob, ln1s + li*Dm, ln1b + li*Dm,
                                     ap ? T1 : qio, ap ? T1s : qios);
        if (ap) {
            gemmHL(T1s, W1s + (size_t)li * 256 * 2048, 2048, b1 + li*FF,
                   nullptr, 0, Hfs, 1024, MTOK, 2048, 512, 1);
            gemmHL(Hfs, W2s + (size_t)li * 1024 * 512, 512, b2 + li*512,
                   Ob, 512, nullptr, 0, MTOK, 512, 2048, 0);
            ln_add_kernel<<<MTOK, 128>>>(T1, Ob, ln2s + li*Dm, ln2b + li*Dm, qio, qios);
        }
    }

    concat_kernel<<<MTOK, 256>>>(xs, x0s, Ccs);
    gemmHL(Ccs, oW0s, 512,  ob0, nullptr, 0, M1s, 256, MTOK, 512,  1024, 1);
    gemmHL(M1s, oW1s, 1024, ob1, nullptr, 0, M2s, 512, MTOK, 1024, 512,  1);
    gemmHL(M2s, oW2s, 1000, ob2, out, 1000, nullptr, 0, MTOK, 1000, 1024, 0);
}